// round 17
// baseline (speedup 1.0000x reference)
#include <cuda_runtime.h>
#include <math.h>

#define Bk   64
#define Tk   512
#define Dd   96
#define TYk  512

typedef unsigned long long u64;

__device__ __forceinline__ u64 ffma2(u64 a, u64 b, u64 c) {
    u64 d;
    asm("fma.rn.f32x2 %0, %1, %2, %3;" : "=l"(d) : "l"(a), "l"(b), "l"(c));
    return d;
}
__device__ __forceinline__ u64 pack2(float lo, float hi) {
    u64 d; asm("mov.b64 %0, {%1, %2};" : "=l"(d) : "f"(lo), "f"(hi)); return d;
}
__device__ __forceinline__ float2 unpack2(u64 v) {
    float2 r; asm("mov.b64 {%0, %1}, %2;" : "=f"(r.x), "=f"(r.y) : "l"(v)); return r;
}

// Scratch -------------------------------------------------------------------
__device__ float g_coeffs1[64 * 128];   // fh=1 partial coeffs
__device__ int   g_flag[64];            // zero-initialized; reset by consumer

#define RP 385                          // reduction row pitch (bank-safe)
#define DYN_FLOATS (2 * 32 * RP)        // 24640 >= 8*3072 pipeline buffer
#define DYN_SMEM   (DYN_FLOATS * 4)

// ---- cp.async chunk streaming: chunk = 32 timesteps x 48-float half -------
// buf[c&7]: X at +0 (32x48), M at +1536 (32x48). One 16B LDGSTS per thread.
__device__ __forceinline__ void issue_chunk(
    float* dyn, const float* Xb, const float* Mb, int c, int tid)
{
    float* buf = dyn + (c & 7) * 3072;
    int half = (tid >= 384);
    int s = half ? tid - 384 : tid;          // 0..383
    int row = s / 12, seg = s - row * 12;    // 32 rows x 12 x 16B
    const float* g = (half ? Mb : Xb) + (c * 32 + row) * 96 + seg * 4;
    float* sm = buf + half * 1536 + row * 48 + seg * 4;
    unsigned sa = (unsigned)__cvta_generic_to_shared(sm);
    asm volatile("cp.async.cg.shared.global [%0], [%1], 16;"
                 :: "r"(sa), "l"(g) : "memory");
}
#define CP_COMMIT() asm volatile("cp.async.commit_group;" ::: "memory")

// ---------------------------------------------------------------------------
// Fused kernel. grid = (2 f-halves, 64 b) x 768 threads.
// ---------------------------------------------------------------------------
__global__ __launch_bounds__(768) void fused_kernel(
    const float* __restrict__ timesteps, const float* __restrict__ X,
    const float* __restrict__ Mm,        const float* __restrict__ te_w,
    const float* __restrict__ te_b,      const float* __restrict__ ow,
    const float* __restrict__ query,     const float* __restrict__ q_w,
    const float* __restrict__ q_b,       const float* __restrict__ k_w,
    const float* __restrict__ k_b,       const float* __restrict__ ob,
    const float* __restrict__ y_ts,      const float* __restrict__ w1,
    const float* __restrict__ b1,        const float* __restrict__ w2,
    const float* __restrict__ b2,        float* __restrict__ out)
{
    extern __shared__ __align__(16) float dyn[];   // stream buf, then reduction

    // ---- attention statics ----
    __shared__ __align__(16) float s_vt[128][8];
    __shared__ __align__(16) float s_et[512][8];
    __shared__ float s_qbuf[512];
    __shared__ float s_xa[8 * 48];
    __shared__ float s_den[8 * 48];
    __shared__ float s_cl[12][64];
    __shared__ float s_c[8];
    __shared__ float sP[8], sQc[8];
    // ---- decoder statics ----
    __shared__ float s_co[128], s_co1[128];
    __shared__ float sc0[64], sc1[64];
    __shared__ float sA[128], sB[128];
    __shared__ float pA[4][128], pB[4][128];
    __shared__ float C0p[4][96], C1p[4][96];
    __shared__ float C0[96], C1[96];
    __shared__ float sy[512];
    __shared__ float redmin[16], redmax[16];
    __shared__ float s_ymin, s_ymax;
    __shared__ float crA[128], crB[128];
    __shared__ int   crI[128];
    __shared__ int   s_ncross;

    int fh = blockIdx.x;
    int b  = blockIdx.y;
    int tid = threadIdx.x;
    int lane = tid & 31, warp = tid >> 5;

    // ================= Stream launch: chunks 0..7 in flight ================
    const float* Xb = X  + (size_t)b * Tk * Dd + fh * 48;
    const float* Mb = Mm + (size_t)b * Tk * Dd + fh * 48;
    #pragma unroll
    for (int c = 0; c < 8; ++c) { issue_chunk(dyn, Xb, Mb, c, tid); CP_COMMIT(); }

    // ================= Phase P: per-block precompute =======================
    float* s_q  = &s_qbuf[0];
    float* s_qp = &s_qbuf[256];
    if (tid < 256) s_q[tid] = query[tid];
    {
        int rg = tid >> 6;
        int l = tid & 63;
        float a = 0.f;
        #pragma unroll 4
        for (int r = rg; r < 192; r += 12) {
            int h = r / 48, jj = r - h * 48;
            a += ow[(h * 192 + 96 + fh * 48 + jj) * 64 + l];
        }
        s_cl[rg][l] = a;
    }
    __syncthreads();
    if (tid < 256) {
        int p = tid >> 7, e = tid & 127;
        float acc = q_b[e];
        #pragma unroll 8
        for (int i = 0; i < 128; ++i)
            acc = fmaf(s_q[p * 128 + i], q_w[i * 128 + e], acc);
        s_qp[tid] = acc;
    }
    __syncthreads();
    for (int idx = tid; idx < 1024; idx += 768) {
        int hp = idx >> 7, ein = idx & 127;
        int h = hp >> 1, p = hp & 1;
        const float4* kr = (const float4*)(k_w + ein * 128 + h * 32);
        const float*  qp = &s_qp[p * 128 + h * 32];
        float acc = 0.f;
        #pragma unroll
        for (int d4 = 0; d4 < 8; ++d4) {
            float4 kv = __ldg(&kr[d4]);
            acc += qp[d4 * 4] * kv.x + qp[d4 * 4 + 1] * kv.y
                 + qp[d4 * 4 + 2] * kv.z + qp[d4 * 4 + 3] * kv.w;
        }
        s_vt[ein][hp] = acc;
    }
    if (tid < 8) {
        int h = tid >> 1, p = tid & 1;
        float acc = 0.f;
        #pragma unroll
        for (int d = 0; d < 32; ++d)
            acc = fmaf(s_qp[p * 128 + h * 32 + d], k_b[h * 32 + d], acc);
        s_c[tid] = acc;
    }
    __syncthreads();

    // ---- fold linear emb lanes (e%4 != 0) into per-hp P, Q ----
    if (tid < 256) {
        int hp = tid >> 5, ln = tid & 31;
        float pPv = 0.f, pQv = 0.f;
        #pragma unroll
        for (int j = 1; j < 4; ++j) {
            int e = 4 * ln + j;
            float v = s_vt[e][hp];
            pPv = fmaf(v, __ldg(&te_w[e]), pPv);
            pQv = fmaf(v, __ldg(&te_b[e]), pQv);
        }
        #pragma unroll
        for (int o = 16; o; o >>= 1) {
            pPv += __shfl_xor_sync(0xffffffffu, pPv, o);
            pQv += __shfl_xor_sync(0xffffffffu, pQv, o);
        }
        if (ln == 0) { sP[hp] = pPv; sQc[hp] = pQv + s_c[hp]; }
    }
    __syncthreads();

    // ================= Phase A: scores -> exp ==============================
    if (tid < 512) {
        float ts = timesteps[b * Tk + tid];
        u64 acc2[4];
        #pragma unroll
        for (int q = 0; q < 4; ++q) {
            float b0 = fmaf(ts, sP[2 * q],     sQc[2 * q]);
            float b1v = fmaf(ts, sP[2 * q + 1], sQc[2 * q + 1]);
            acc2[q] = pack2(b0, b1v);
        }
        #pragma unroll 4
        for (int es = 0; es < 32; ++es) {
            int e = 4 * es;
            float sv = __sinf(fmaf(ts, __ldg(&te_w[e]), __ldg(&te_b[e])));
            u64 svd = pack2(sv, sv);
            ulonglong2 va = *(const ulonglong2*)&s_vt[e][0];
            ulonglong2 vb = *(const ulonglong2*)&s_vt[e][4];
            acc2[0] = ffma2(svd, va.x, acc2[0]);
            acc2[1] = ffma2(svd, va.y, acc2[1]);
            acc2[2] = ffma2(svd, vb.x, acc2[2]);
            acc2[3] = ffma2(svd, vb.y, acc2[3]);
        }
        const float scale = 0.17677669529663687f;  // 1/sqrt(32)
        float2 a0 = unpack2(acc2[0]), a1 = unpack2(acc2[1]);
        float2 a2 = unpack2(acc2[2]), a3 = unpack2(acc2[3]);
        *(float4*)&s_et[tid][0] = make_float4(
            __expf(a0.x * scale), __expf(a0.y * scale),
            __expf(a1.x * scale), __expf(a1.y * scale));
        *(float4*)&s_et[tid][4] = make_float4(
            __expf(a2.x * scale), __expf(a2.y * scale),
            __expf(a3.x * scale), __expf(a3.y * scale));
    }

    // ================= Phase C: pipelined smem consume =====================
    int tsub = tid / 24, f2l = tid - tsub * 24;
    u64 num[2][4], den[2][4];
    #pragma unroll
    for (int fs = 0; fs < 2; ++fs)
        #pragma unroll
        for (int q = 0; q < 4; ++q) { num[fs][q] = 0ull; den[fs][q] = 0ull; }

#define CONSUME(Q) { \
        const float* bufc = dyn + ((Q) & 7) * 3072; \
        float2 x2 = *(const float2*)(bufc + tsub * 48 + 2 * f2l); \
        float2 m2 = *(const float2*)(bufc + 1536 + tsub * 48 + 2 * f2l); \
        int t = (Q) * 32 + tsub; \
        ulonglong2 e01 = *(const ulonglong2*)&s_et[t][0]; \
        ulonglong2 e23 = *(const ulonglong2*)&s_et[t][4]; \
        u64 m0  = pack2(m2.x, m2.x); \
        u64 m1  = pack2(m2.y, m2.y); \
        float xma = m2.x * x2.x, xmb = m2.y * x2.y; \
        u64 xm0 = pack2(xma, xma); \
        u64 xm1 = pack2(xmb, xmb); \
        den[0][0] = ffma2(e01.x, m0, den[0][0]); \
        den[0][1] = ffma2(e01.y, m0, den[0][1]); \
        den[0][2] = ffma2(e23.x, m0, den[0][2]); \
        den[0][3] = ffma2(e23.y, m0, den[0][3]); \
        num[0][0] = ffma2(e01.x, xm0, num[0][0]); \
        num[0][1] = ffma2(e01.y, xm0, num[0][1]); \
        num[0][2] = ffma2(e23.x, xm0, num[0][2]); \
        num[0][3] = ffma2(e23.y, xm0, num[0][3]); \
        den[1][0] = ffma2(e01.x, m1, den[1][0]); \
        den[1][1] = ffma2(e01.y, m1, den[1][1]); \
        den[1][2] = ffma2(e23.x, m1, den[1][2]); \
        den[1][3] = ffma2(e23.y, m1, den[1][3]); \
        num[1][0] = ffma2(e01.x, xm1, num[1][0]); \
        num[1][1] = ffma2(e01.y, xm1, num[1][1]); \
        num[1][2] = ffma2(e23.x, xm1, num[1][2]); \
        num[1][3] = ffma2(e23.y, xm1, num[1][3]); \
    }

#define PSTEP(Q0, WN) \
    asm volatile("cp.async.wait_group %0;" :: "n"(WN) : "memory"); \
    __syncthreads(); \
    CONSUME(Q0) CONSUME((Q0) + 1) \
    __syncthreads(); \
    if ((Q0) + 8 < 16) { \
        issue_chunk(dyn, Xb, Mb, (Q0) + 8, tid); CP_COMMIT(); \
        issue_chunk(dyn, Xb, Mb, (Q0) + 9, tid); CP_COMMIT(); \
    }

    PSTEP(0, 6)  PSTEP(2, 6)  PSTEP(4, 6)  PSTEP(6, 6)
    PSTEP(8, 6)  PSTEP(10, 4) PSTEP(12, 2) PSTEP(14, 0)

#undef PSTEP
#undef CONSUME

    // ---- single-pass reduction through dynamic smem (2 barriers) ----
    float* s_rn = dyn;               // [32][RP]
    float* s_rd = dyn + 32 * RP;     // [32][RP]
    #pragma unroll
    for (int fs = 0; fs < 2; ++fs) {
        int fl = 2 * f2l + fs;
        #pragma unroll
        for (int qq = 0; qq < 4; ++qq) {
            float2 vn = unpack2(num[fs][qq]);
            s_rn[tsub * RP + (2 * qq) * 48 + fl]     = vn.x;
            s_rn[tsub * RP + (2 * qq + 1) * 48 + fl] = vn.y;
            float2 vd = unpack2(den[fs][qq]);
            s_rd[tsub * RP + (2 * qq) * 48 + fl]     = vd.x;
            s_rd[tsub * RP + (2 * qq + 1) * 48 + fl] = vd.y;
        }
    }
    __syncthreads();
    {
        int slot = (tid < 384) ? tid : tid - 384;
        const float* base = (tid < 384) ? s_rn : s_rd;
        float a0 = 0.f, a1 = 0.f, a2 = 0.f, a3 = 0.f;
        #pragma unroll
        for (int r = 0; r < 32; r += 4) {
            a0 += base[(r + 0) * RP + slot];
            a1 += base[(r + 1) * RP + slot];
            a2 += base[(r + 2) * RP + slot];
            a3 += base[(r + 3) * RP + slot];
        }
        float r_acc = (a0 + a1) + (a2 + a3);
        if (tid >= 384) s_den[slot] = r_acc;
        __syncthreads();
        if (tid < 384) s_xa[tid] = r_acc / s_den[tid];
    }
    __syncthreads();

    // ================= Phase D: partial coeffs =============================
    float* s_scr = (float*)s_et;
    {
        int outIdx = tid & 127;
        int seg = tid >> 7;
        int p = outIdx >> 6, l = outIdx & 63;
        float acc = 0.f;
        #pragma unroll 4
        for (int r = seg * 32; r < seg * 32 + 32; ++r) {
            int h = r / 48, fl = r - h * 48;
            acc = fmaf(s_xa[(h * 2 + p) * 48 + fl],
                       ow[(h * 192 + fh * 48 + fl) * 64 + l], acc);
        }
        s_scr[tid] = acc;
    }
    __syncthreads();
    float cv = 0.f;
    if (tid < 128) {
        int l = tid & 63;
        cv = (fh == 0) ? ob[l] : 0.f;
        #pragma unroll
        for (int g = 0; g < 12; ++g) cv += s_cl[g][l];
        #pragma unroll
        for (int seg = 0; seg < 6; ++seg) cv += s_scr[seg * 128 + tid];
    }

    // ================= Producer epilogue (fh == 1) =========================
    if (fh == 1) {
        if (tid < 128) g_coeffs1[b * 128 + tid] = cv;
        __threadfence();
        __syncthreads();
        if (tid == 0) atomicExch(&g_flag[b], 1);
        return;
    }

    // ================= Consumer: decoder ===================================
    if (tid < 128) s_co[tid] = cv;
    if (tid == 0) s_ncross = 0;
    if (tid < 512) {
        float yv = __ldg(&y_ts[(size_t)b * TYk + tid]);
        sy[tid] = yv;
        float mn = yv, mx = yv;
        #pragma unroll
        for (int o = 16; o; o >>= 1) {
            mn = fminf(mn, __shfl_xor_sync(0xffffffffu, mn, o));
            mx = fmaxf(mx, __shfl_xor_sync(0xffffffffu, mx, o));
        }
        if (lane == 0) { redmin[warp] = mn; redmax[warp] = mx; }
    }
    __syncthreads();
    if (tid == 0) {
        float mn = redmin[0], mx = redmax[0];
        #pragma unroll
        for (int wv = 1; wv < 16; ++wv) {
            mn = fminf(mn, redmin[wv]);
            mx = fmaxf(mx, redmax[wv]);
        }
        s_ymin = mn; s_ymax = mx;
        while (atomicAdd(&g_flag[b], 0) == 0) __nanosleep(64);
        __threadfence();
    }
    __syncthreads();
    if (tid < 128) s_co1[tid] = g_coeffs1[b * 128 + tid];
    __syncthreads();
    if (tid == 0) atomicExch(&g_flag[b], 0);
    if (tid < 64)       sc0[tid] = s_co[tid] + s_co1[tid];
    else if (tid < 128) sc1[tid - 64] = s_co[tid] + s_co1[tid];
    __syncthreads();

    // ---- A/B split-K (direct LDG of w1) ----
    if (tid < 512) {
        int g = tid >> 7, i = tid & 127;
        float a = 0.f, bb = 0.f;
        #pragma unroll
        for (int l = g * 16; l < g * 16 + 16; ++l) {
            float w = __ldg(&w1[l * 128 + i]);
            a  = fmaf(sc0[l], w, a);
            bb = fmaf(sc1[l], w, bb);
        }
        pA[g][i] = a; pB[g][i] = bb;
    }
    __syncthreads();
    // ---- classify units over [ymin, ymax] ----
    if (tid < 128) {
        int i = tid;
        float a  = b1[i] + pA[0][i] + pA[1][i] + pA[2][i] + pA[3][i];
        float bb = pB[0][i] + pB[1][i] + pB[2][i] + pB[3][i];
        float h0 = fmaf(s_ymin, bb, a);
        float h1 = fmaf(s_ymax, bb, a);
        bool a0 = h0 > 0.f, a1 = h1 > 0.f;
        bool full = a0 && a1;
        sA[i] = full ? a  : 0.f;
        sB[i] = full ? bb : 0.f;
        if (a0 != a1) {
            int slot = atomicAdd(&s_ncross, 1);
            crA[slot] = a; crB[slot] = bb; crI[slot] = i;
        }
    }
    __syncthreads();
    // ---- base C0/C1 partials (direct LDG of w2) ----
    if (tid < 384) {
        int g = tid / 96, j = tid - g * 96;
        float c0 = 0.f, c1 = 0.f;
        #pragma unroll 8
        for (int i = g * 32; i < g * 32 + 32; ++i) {
            float w = __ldg(&w2[i * 96 + j]);
            c0 = fmaf(sA[i], w, c0);
            c1 = fmaf(sB[i], w, c1);
        }
        C0p[g][j] = c0; C1p[g][j] = c1;
    }
    __syncthreads();
    if (tid < 96) {
        C0[tid] = C0p[0][tid] + C0p[1][tid] + C0p[2][tid] + C0p[3][tid];
        C1[tid] = C1p[0][tid] + C1p[1][tid] + C1p[2][tid] + C1p[3][tid];
    }
    __syncthreads();

    // ---- eval (first 512 threads) ----
    if (tid < 512) {
        int yg = tid >> 3, jg = tid & 7;
        int j0 = jg * 12;
        int ncross = s_ncross;
        float c0r[12], c1r[12], b2v[12];
        #pragma unroll
        for (int u = 0; u < 12; ++u) {
            c0r[u] = C0[j0 + u];
            c1r[u] = C1[j0 + u];
            b2v[u] = b2[j0 + u];
        }
        #pragma unroll 2
        for (int r = 0; r < 8; ++r) {
            int ty = r * 64 + yg;
            float y = sy[ty];
            float ov[12];
            #pragma unroll
            for (int u = 0; u < 12; ++u)
                ov[u] = fmaf(y, c1r[u], c0r[u]) + b2v[u];
            for (int k = 0; k < ncross; ++k) {     // usually 0 iterations
                float h = fmaf(y, crB[k], crA[k]);
                if (h > 0.f) {
                    const float* wr = w2 + crI[k] * 96 + j0;
                    #pragma unroll
                    for (int u = 0; u < 12; ++u)
                        ov[u] = fmaf(h, __ldg(&wr[u]), ov[u]);
                }
            }
            float* o = out + ((size_t)b * TYk + ty) * Dd + j0;
            #pragma unroll
            for (int u = 0; u < 12; u += 2)
                *(float2*)&o[u] = make_float2(ov[u], ov[u + 1]);
        }
    }
}

// ---------------------------------------------------------------------------
extern "C" void kernel_launch(void* const* d_in, const int* in_sizes, int n_in,
                              void* d_out, int out_size)
{
    const float* timesteps = (const float*)d_in[0];
    const float* X         = (const float*)d_in[1];
    const float* Mm        = (const float*)d_in[2];
    const float* y_ts      = (const float*)d_in[3];
    const float* te_w      = (const float*)d_in[4];
    const float* te_b      = (const float*)d_in[5];
    const float* query     = (const float*)d_in[6];
    const float* q_w       = (const float*)d_in[7];
    const float* q_b       = (const float*)d_in[8];
    const float* k_w       = (const float*)d_in[9];
    const float* k_b       = (const float*)d_in[10];
    const float* ow        = (const float*)d_in[11];
    const float* ob        = (const float*)d_in[12];
    const float* w1        = (const float*)d_in[13];
    const float* b1        = (const float*)d_in[14];
    const float* w2        = (const float*)d_in[15];
    const float* b2        = (const float*)d_in[16];
    float* out = (float*)d_out;

    cudaFuncSetAttribute(fused_kernel,
                         cudaFuncAttributeMaxDynamicSharedMemorySize, DYN_SMEM);

    fused_kernel<<<dim3(2, 64), 768, DYN_SMEM>>>(
        timesteps, X, Mm, te_w, te_b, ow, query, q_w, q_b, k_w, k_b, ob,
        y_ts, w1, b1, w2, b2, out);
}